// round 2
// baseline (speedup 1.0000x reference)
#include <cuda_runtime.h>

// Problem constants (fixed by the dataset): u (8,2048,1024) f32, A/B/C/D (1024,1024) f32.
constexpr int N_DIM  = 1024;
constexpr int T_LEN  = 2048;
constexpr int CHUNK  = 64;           // scan chunk length (a^64 underflows -> carries ~0, but exact algo kept)

// Scratch: Bu / X in-place buffer (64 MB) + chunk carries (1 MB). __device__ globals (no allocation).
__device__ float g_Bu[8L * 2048 * 1024];
__device__ float g_carry[8 * (T_LEN / CHUNK) * N_DIM];

// ---------------------------------------------------------------------------
// NT GEMM: out[m,n] = sum_k A[m,k]*B[n,k]  (+ sum_k A2[m,k]*B2[n,k] if DUAL)
// A: [M,K] row-major, B: [N,K] row-major. M%128==0, N%128==0, K%16==0 assumed.
// 128x128 block tile, 8x8 per thread, BK=16, register-prefetch pipeline.
// ---------------------------------------------------------------------------
template <bool DUAL>
__global__ void __launch_bounds__(256, 2)
gemm_nt(const float* __restrict__ A, const float* __restrict__ B,
        const float* __restrict__ A2, const float* __restrict__ B2,
        float* __restrict__ Cout, int M, int N, int K)
{
    constexpr int BM = 128, BN = 128, BK = 16;
    __shared__ float As[BK][BM + 4];
    __shared__ float Bs[BK][BN + 4];

    const int tid  = threadIdx.x;
    const int m0   = blockIdx.y * BM;
    const int n0   = blockIdx.x * BN;

    // load mapping: each thread loads 2 float4 per operand per tile
    const int arow = tid >> 2;            // 0..63 (second load is +64)
    const int acol = (tid & 3) * 4;       // 0,4,8,12 within BK

    // compute mapping
    const int tx = tid & 15;              // n micro-tile
    const int ty = tid >> 4;              // m micro-tile

    float acc[8][8] = {};

    #pragma unroll
    for (int pass = 0; pass < (DUAL ? 2 : 1); ++pass) {
        const float* Ag = (DUAL && pass) ? A2 : A;
        const float* Bg = (DUAL && pass) ? B2 : B;

        const float* Aptr = Ag + (size_t)(m0 + arow) * K + acol;
        const float* Bptr = Bg + (size_t)(n0 + arow) * K + acol;

        float4 a0 = *(const float4*)(Aptr);
        float4 a1 = *(const float4*)(Aptr + (size_t)64 * K);
        float4 b0 = *(const float4*)(Bptr);
        float4 b1 = *(const float4*)(Bptr + (size_t)64 * K);

        for (int k0 = 0; k0 < K; k0 += BK) {
            // regs -> smem (transposed, padded)
            As[acol + 0][arow]      = a0.x;
            As[acol + 1][arow]      = a0.y;
            As[acol + 2][arow]      = a0.z;
            As[acol + 3][arow]      = a0.w;
            As[acol + 0][arow + 64] = a1.x;
            As[acol + 1][arow + 64] = a1.y;
            As[acol + 2][arow + 64] = a1.z;
            As[acol + 3][arow + 64] = a1.w;
            Bs[acol + 0][arow]      = b0.x;
            Bs[acol + 1][arow]      = b0.y;
            Bs[acol + 2][arow]      = b0.z;
            Bs[acol + 3][arow]      = b0.w;
            Bs[acol + 0][arow + 64] = b1.x;
            Bs[acol + 1][arow + 64] = b1.y;
            Bs[acol + 2][arow + 64] = b1.z;
            Bs[acol + 3][arow + 64] = b1.w;
            __syncthreads();

            // prefetch next K tile into regs (overlaps with compute below)
            if (k0 + BK < K) {
                a0 = *(const float4*)(Aptr + k0 + BK);
                a1 = *(const float4*)(Aptr + (size_t)64 * K + k0 + BK);
                b0 = *(const float4*)(Bptr + k0 + BK);
                b1 = *(const float4*)(Bptr + (size_t)64 * K + k0 + BK);
            }

            #pragma unroll
            for (int k = 0; k < BK; ++k) {
                float ra[8], rb[8];
                *(float4*)&ra[0] = *(const float4*)&As[k][ty * 8];
                *(float4*)&ra[4] = *(const float4*)&As[k][ty * 8 + 4];
                *(float4*)&rb[0] = *(const float4*)&Bs[k][tx * 8];
                *(float4*)&rb[4] = *(const float4*)&Bs[k][tx * 8 + 4];
                #pragma unroll
                for (int i = 0; i < 8; ++i)
                    #pragma unroll
                    for (int j = 0; j < 8; ++j)
                        acc[i][j] = fmaf(ra[i], rb[j], acc[i][j]);
            }
            __syncthreads();
        }
    }

    // write out (float4 stores)
    #pragma unroll
    for (int i = 0; i < 8; ++i) {
        const int row = m0 + ty * 8 + i;
        float4 v0 = make_float4(acc[i][0], acc[i][1], acc[i][2], acc[i][3]);
        float4 v1 = make_float4(acc[i][4], acc[i][5], acc[i][6], acc[i][7]);
        *(float4*)&Cout[(size_t)row * N + n0 + tx * 8]     = v0;
        *(float4*)&Cout[(size_t)row * N + n0 + tx * 8 + 4] = v1;
    }
}

// ---------------------------------------------------------------------------
// Chunked parallel scan over T, in-place on g_Bu:  x_t = a * x_{t-1} + Bu_t
// phase1: local scan per (b, chunk, n), store chunk-final into g_carry
// phase2: sequential combine of chunk carries per (b, n)
// phase3: add carried prefix back into each chunk
// ---------------------------------------------------------------------------
__global__ void scan_phase1(const float* __restrict__ Afull, int batch)
{
    const int nChunks = T_LEN / CHUNK;
    int id = blockIdx.x * blockDim.x + threadIdx.x;
    int n  = id & (N_DIM - 1);
    int bc = id >> 10;                 // b*nChunks + c
    if (bc >= batch * nChunks) return;
    int c  = bc % nChunks;
    int b  = bc / nChunks;

    const float a = Afull[(size_t)n * N_DIM + n];   // diag(A)
    size_t base = ((size_t)(b * T_LEN + c * CHUNK)) * N_DIM + n;

    float x = 0.0f;
    #pragma unroll 8
    for (int t = 0; t < CHUNK; ++t) {
        float v = g_Bu[base + (size_t)t * N_DIM];
        x = fmaf(x, a, v);
        g_Bu[base + (size_t)t * N_DIM] = x;
    }
    g_carry[(size_t)bc * N_DIM + n] = x;
}

__global__ void scan_phase2(const float* __restrict__ Afull, int batch)
{
    const int nChunks = T_LEN / CHUNK;
    int id = blockIdx.x * blockDim.x + threadIdx.x;
    if (id >= batch * N_DIM) return;
    int n = id & (N_DIM - 1);
    int b = id >> 10;

    float a  = Afull[(size_t)n * N_DIM + n];
    float aC = a;                      // a^CHUNK via repeated squaring (CHUNK=64=2^6)
    #pragma unroll
    for (int i = 0; i < 6; ++i) aC *= aC;

    float S = 0.0f;                    // true state entering chunk c
    for (int c = 0; c < nChunks; ++c) {
        size_t idx = (size_t)(b * nChunks + c) * N_DIM + n;
        float L = g_carry[idx];        // local chunk-final
        g_carry[idx] = S;              // overwrite with incoming state
        S = fmaf(aC, S, L);
    }
}

__global__ void scan_phase3(const float* __restrict__ Afull, int batch)
{
    const int nChunks = T_LEN / CHUNK;
    int id = blockIdx.x * blockDim.x + threadIdx.x;
    int n  = id & (N_DIM - 1);
    int bc = id >> 10;
    if (bc >= batch * nChunks) return;
    int c  = bc % nChunks;
    int b  = bc / nChunks;

    float S = g_carry[(size_t)bc * N_DIM + n];
    if (S == 0.0f) return;             // chunk 0 and fully-decayed carries skip all traffic

    const float a = Afull[(size_t)n * N_DIM + n];
    size_t base = ((size_t)(b * T_LEN + c * CHUNK)) * N_DIM + n;

    float f = a;                       // x_{t0+t} = L_t + a^{t+1} * S
    #pragma unroll 8
    for (int t = 0; t < CHUNK; ++t) {
        size_t idx = base + (size_t)t * N_DIM;
        g_Bu[idx] = fmaf(f, S, g_Bu[idx]);
        f *= a;
    }
}

// ---------------------------------------------------------------------------
extern "C" void kernel_launch(void* const* d_in, const int* in_sizes, int n_in,
                              void* d_out, int out_size)
{
    const float* u = (const float*)d_in[0];   // (batch, T, m)
    const float* A = (const float*)d_in[1];   // (n, n)
    const float* B = (const float*)d_in[2];   // (n, m)
    const float* C = (const float*)d_in[3];   // (p, n)
    const float* D = (const float*)d_in[4];   // (p, m)
    float* out = (float*)d_out;

    const int M     = in_sizes[0] / N_DIM;    // batch * T = 16384
    const int batch = M / T_LEN;              // 8
    const int nChunks = T_LEN / CHUNK;        // 32

    float* Bu_ptr = nullptr;
    cudaGetSymbolAddress((void**)&Bu_ptr, g_Bu);

    dim3 gemm_grid(N_DIM / 128, M / 128);

    // 1) Bu = u @ B^T
    gemm_nt<false><<<gemm_grid, 256>>>(u, B, nullptr, nullptr, Bu_ptr, M, N_DIM, N_DIM);

    // 2) in-place scan over T
    int p1_threads = batch * nChunks * N_DIM;
    scan_phase1<<<(p1_threads + 255) / 256, 256>>>(A, batch);
    int p2_threads = batch * N_DIM;
    scan_phase2<<<(p2_threads + 255) / 256, 256>>>(A, batch);
    scan_phase3<<<(p1_threads + 255) / 256, 256>>>(A, batch);

    // 3) y = X @ C^T + u @ D^T  (fused dual-K GEMM)
    gemm_nt<true><<<gemm_grid, 256>>>(Bu_ptr, C, u, D, out, M, N_DIM, N_DIM);
}

// round 4
// speedup vs baseline: 2.0606x; 2.0606x over previous
#include <cuda_runtime.h>
#include <cuda_bf16.h>
#include <cstdint>

// Problem constants (fixed): u (8,2048,1024) f32, A/B/C/D (1024,1024) f32.
constexpr int N_DIM = 1024;
constexpr int T_LEN = 2048;
constexpr int CHUNK = 64;

// Scratch (__device__ globals; no allocation allowed).
__device__ float g_Bu[16777216];          // Bu / X, f32 (64MB)
__device__ float g_carry[262144];
__device__ __nv_bfloat16 g_uh[16777216], g_ul[16777216];   // u hi/lo
__device__ __nv_bfloat16 g_Xh[16777216], g_Xl[16777216];   // X hi/lo
__device__ __nv_bfloat16 g_Bh[1048576],  g_Bl[1048576];
__device__ __nv_bfloat16 g_Ch[1048576],  g_Cl[1048576];
__device__ __nv_bfloat16 g_Dh[1048576],  g_Dl[1048576];

// ---------------------------------------------------------------------------
// helpers
// ---------------------------------------------------------------------------
__device__ __forceinline__ uint32_t smem_u32(const void* p) {
    uint32_t a;
    asm("{ .reg .u64 t; cvta.to.shared.u64 t, %1; cvt.u32.u64 %0, t; }" : "=r"(a) : "l"(p));
    return a;
}
__device__ __forceinline__ void cp_async16(uint32_t dst, const void* src) {
    asm volatile("cp.async.cg.shared.global [%0], [%1], 16;" :: "r"(dst), "l"(src));
}
__device__ __forceinline__ void cp_commit() {
    asm volatile("cp.async.commit_group;");
}
__device__ __forceinline__ void cp_wait1() {
    asm volatile("cp.async.wait_group 1;");
}
__device__ __forceinline__ void ldsm4(uint32_t* r, uint32_t addr) {
    asm volatile("ldmatrix.sync.aligned.m8n8.x4.shared.b16 {%0,%1,%2,%3}, [%4];"
                 : "=r"(r[0]), "=r"(r[1]), "=r"(r[2]), "=r"(r[3]) : "r"(addr));
}
__device__ __forceinline__ void mma16816(float* d, const uint32_t* a, const uint32_t* b) {
    asm volatile(
        "mma.sync.aligned.m16n8k16.row.col.f32.bf16.bf16.f32 "
        "{%0,%1,%2,%3}, {%4,%5,%6,%7}, {%8,%9}, {%0,%1,%2,%3};"
        : "+f"(d[0]), "+f"(d[1]), "+f"(d[2]), "+f"(d[3])
        : "r"(a[0]), "r"(a[1]), "r"(a[2]), "r"(a[3]), "r"(b[0]), "r"(b[1]));
}
__device__ __forceinline__ uint32_t pk_bf16(__nv_bfloat16 a, __nv_bfloat16 b) {
    return (uint32_t)__bfloat16_as_ushort(a) | ((uint32_t)__bfloat16_as_ushort(b) << 16);
}

// ---------------------------------------------------------------------------
// split f32 -> bf16 hi + bf16 lo (lo = bf16(x - f32(hi)))
// ---------------------------------------------------------------------------
__global__ void split_f32(const float4* __restrict__ src,
                          uint2* __restrict__ hi, uint2* __restrict__ lo, int n4)
{
    int i = blockIdx.x * blockDim.x + threadIdx.x;
    if (i >= n4) return;
    float4 v = src[i];
    __nv_bfloat16 h0 = __float2bfloat16(v.x), h1 = __float2bfloat16(v.y);
    __nv_bfloat16 h2 = __float2bfloat16(v.z), h3 = __float2bfloat16(v.w);
    __nv_bfloat16 l0 = __float2bfloat16(v.x - __bfloat162float(h0));
    __nv_bfloat16 l1 = __float2bfloat16(v.y - __bfloat162float(h1));
    __nv_bfloat16 l2 = __float2bfloat16(v.z - __bfloat162float(h2));
    __nv_bfloat16 l3 = __float2bfloat16(v.w - __bfloat162float(h3));
    hi[i] = make_uint2(pk_bf16(h0, h1), pk_bf16(h2, h3));
    lo[i] = make_uint2(pk_bf16(l0, l1), pk_bf16(l2, l3));
}

// ---------------------------------------------------------------------------
// bf16 3-product NT GEMM via mma.sync: out[m,n] = sum_k A[m,k]*B[n,k]
// (+ A2*B2 if DUAL).  A,B pre-split into hi/lo bf16 [*, K] row-major.
// 128x128x32 tiles, 256 threads (2x4 warps, 64x32 warp tile), 3-stage cp.async.
// ---------------------------------------------------------------------------
constexpr int BM = 128, BN = 128, BK = 32;
constexpr int BKP = 40;                      // halves per row incl. 16B pad
constexpr int TILE_B = BM * BKP * 2;         // 10240 bytes per matrix tile
constexpr int STAGE_B = 4 * TILE_B;          // Ah, Al, Bh, Bl
constexpr int STAGES = 3;
constexpr int GEMM_SMEM = STAGES * STAGE_B;  // 122880

template <bool DUAL>
__global__ void __launch_bounds__(256, 1)
gemm_mma(const __nv_bfloat16* __restrict__ Ah, const __nv_bfloat16* __restrict__ Al,
         const __nv_bfloat16* __restrict__ Bh, const __nv_bfloat16* __restrict__ Bl,
         const __nv_bfloat16* __restrict__ A2h, const __nv_bfloat16* __restrict__ A2l,
         const __nv_bfloat16* __restrict__ B2h, const __nv_bfloat16* __restrict__ B2l,
         float* __restrict__ Cout, int M, int N, int K)
{
    extern __shared__ char smem[];
    const uint32_t sbase = smem_u32(smem);
    const int tid = threadIdx.x, lane = tid & 31, wid = tid >> 5;
    const int wm = wid >> 2, wn = wid & 3;
    const int m0 = blockIdx.y * BM, n0 = blockIdx.x * BN;

    const int IPER = K / BK;                  // 32
    const int KT = DUAL ? 2 * IPER : IPER;

    float acc[4][4][4] = {};

    // loader lambda: stage s <- k-iteration kt
    auto issue = [&](int kt) {
        const bool p2 = DUAL && (kt >= IPER);
        const __nv_bfloat16* ah = p2 ? A2h : Ah;
        const __nv_bfloat16* al = p2 ? A2l : Al;
        const __nv_bfloat16* bh = p2 ? B2h : Bh;
        const __nv_bfloat16* bl = p2 ? B2l : Bl;
        const int k0 = (kt % IPER) * BK;
        const uint32_t st = sbase + (kt % STAGES) * STAGE_B;
        #pragma unroll
        for (int i = 0; i < 2; ++i) {
            const int cid = tid + i * 256;      // 0..511
            const int r = cid >> 2, c = cid & 3;
            const uint32_t dst = st + r * (BKP * 2) + c * 16;
            const size_t goA = (size_t)(m0 + r) * K + k0 + c * 8;
            const size_t goB = (size_t)(n0 + r) * K + k0 + c * 8;
            cp_async16(dst,              ah + goA);
            cp_async16(dst + TILE_B,     al + goA);
            cp_async16(dst + 2 * TILE_B, bh + goB);
            cp_async16(dst + 3 * TILE_B, bl + goB);
        }
    };

    issue(0); cp_commit();
    issue(1); cp_commit();

    // per-lane ldmatrix address bases (byte offsets within a tile)
    const uint32_t a_base = (((wm * 64 + (lane & 15)) * BKP) + ((lane >> 4) << 3)) * 2;
    const uint32_t b_base = (((wn * 32 + (lane & 7) + ((lane >> 4) << 3)) * BKP) +
                             (((lane >> 3) & 1) << 3)) * 2;

    for (int kt = 0; kt < KT; ++kt) {
        cp_wait1();
        __syncthreads();
        if (kt + 2 < KT) issue(kt + 2);
        cp_commit();

        const uint32_t st = sbase + (kt % STAGES) * STAGE_B;
        const uint32_t sAh = st, sAl = st + TILE_B, sBh = st + 2 * TILE_B, sBl = st + 3 * TILE_B;

        #pragma unroll
        for (int k16 = 0; k16 < 2; ++k16) {
            uint32_t ahr[4][4], alr[4][4], bhr[2][4], blr[2][4];
            #pragma unroll
            for (int mi = 0; mi < 4; ++mi) {
                const uint32_t off = a_base + mi * (16 * BKP * 2) + k16 * 32;
                ldsm4(ahr[mi], sAh + off);
                ldsm4(alr[mi], sAl + off);
            }
            #pragma unroll
            for (int nj = 0; nj < 2; ++nj) {
                const uint32_t off = b_base + nj * (16 * BKP * 2) + k16 * 32;
                ldsm4(bhr[nj], sBh + off);
                ldsm4(blr[nj], sBl + off);
            }
            #pragma unroll
            for (int mi = 0; mi < 4; ++mi) {
                #pragma unroll
                for (int nf = 0; nf < 4; ++nf) {
                    const uint32_t* bhp = &bhr[nf >> 1][(nf & 1) * 2];
                    const uint32_t* blp = &blr[nf >> 1][(nf & 1) * 2];
                    mma16816(acc[mi][nf], ahr[mi], bhp);   // hi*hi
                    mma16816(acc[mi][nf], ahr[mi], blp);   // hi*lo
                    mma16816(acc[mi][nf], alr[mi], bhp);   // lo*hi
                }
            }
        }
    }

    // epilogue: d-frag m16n8: d0,d1 -> (row, col..col+1); d2,d3 -> row+8
    #pragma unroll
    for (int mi = 0; mi < 4; ++mi) {
        const int row0 = m0 + wm * 64 + mi * 16 + (lane >> 2);
        #pragma unroll
        for (int nf = 0; nf < 4; ++nf) {
            const int col = n0 + wn * 32 + (nf >> 1) * 16 + (nf & 1) * 8 + (lane & 3) * 2;
            *(float2*)&Cout[(size_t)row0 * N + col] =
                make_float2(acc[mi][nf][0], acc[mi][nf][1]);
            *(float2*)&Cout[(size_t)(row0 + 8) * N + col] =
                make_float2(acc[mi][nf][2], acc[mi][nf][3]);
        }
    }
}

// ---------------------------------------------------------------------------
// Chunked parallel scan over T, in-place on g_Bu:  x_t = a * x_{t-1} + Bu_t
// ---------------------------------------------------------------------------
__global__ void scan_phase1(const float* __restrict__ Afull, int batch)
{
    const int nChunks = T_LEN / CHUNK;
    int id = blockIdx.x * blockDim.x + threadIdx.x;
    int n  = id & (N_DIM - 1);
    int bc = id >> 10;
    if (bc >= batch * nChunks) return;
    int c = bc % nChunks, b = bc / nChunks;

    const float a = Afull[(size_t)n * N_DIM + n];
    size_t base = ((size_t)(b * T_LEN + c * CHUNK)) * N_DIM + n;

    float x = 0.0f;
    #pragma unroll 8
    for (int t = 0; t < CHUNK; ++t) {
        float v = g_Bu[base + (size_t)t * N_DIM];
        x = fmaf(x, a, v);
        g_Bu[base + (size_t)t * N_DIM] = x;
    }
    g_carry[(size_t)bc * N_DIM + n] = x;
}

__global__ void scan_phase2(const float* __restrict__ Afull, int batch)
{
    const int nChunks = T_LEN / CHUNK;
    int id = blockIdx.x * blockDim.x + threadIdx.x;
    if (id >= batch * N_DIM) return;
    int n = id & (N_DIM - 1), b = id >> 10;

    float a  = Afull[(size_t)n * N_DIM + n];
    float aC = a;
    #pragma unroll
    for (int i = 0; i < 6; ++i) aC *= aC;

    float S = 0.0f;
    for (int c = 0; c < nChunks; ++c) {
        size_t idx = (size_t)(b * nChunks + c) * N_DIM + n;
        float L = g_carry[idx];
        g_carry[idx] = S;
        S = fmaf(aC, S, L);
    }
}

__global__ void scan_phase3(const float* __restrict__ Afull, int batch)
{
    const int nChunks = T_LEN / CHUNK;
    int id = blockIdx.x * blockDim.x + threadIdx.x;
    int n  = id & (N_DIM - 1);
    int bc = id >> 10;
    if (bc >= batch * nChunks) return;
    int c = bc % nChunks, b = bc / nChunks;

    float S = g_carry[(size_t)bc * N_DIM + n];
    if (S == 0.0f) return;

    const float a = Afull[(size_t)n * N_DIM + n];
    size_t base = ((size_t)(b * T_LEN + c * CHUNK)) * N_DIM + n;

    float f = a;
    #pragma unroll 8
    for (int t = 0; t < CHUNK; ++t) {
        size_t idx = base + (size_t)t * N_DIM;
        g_Bu[idx] = fmaf(f, S, g_Bu[idx]);
        f *= a;
    }
}

// ---------------------------------------------------------------------------
extern "C" void kernel_launch(void* const* d_in, const int* in_sizes, int n_in,
                              void* d_out, int out_size)
{
    const float* u  = (const float*)d_in[0];   // (batch, T, m)
    const float* A  = (const float*)d_in[1];   // (n, n)
    const float* B  = (const float*)d_in[2];   // (n, m)
    const float* C  = (const float*)d_in[3];   // (p, n)
    const float* Dm = (const float*)d_in[4];   // (p, m)
    float* out = (float*)d_out;

    const int M     = in_sizes[0] / N_DIM;     // 16384
    const int batch = M / T_LEN;               // 8
    const int nChunks = T_LEN / CHUNK;

    float *Bu_p; cudaGetSymbolAddress((void**)&Bu_p, g_Bu);
    __nv_bfloat16 *uh, *ul, *Xh, *Xl, *Bh, *Bl, *Ch, *Cl, *Dh, *Dl;
    cudaGetSymbolAddress((void**)&uh, g_uh); cudaGetSymbolAddress((void**)&ul, g_ul);
    cudaGetSymbolAddress((void**)&Xh, g_Xh); cudaGetSymbolAddress((void**)&Xl, g_Xl);
    cudaGetSymbolAddress((void**)&Bh, g_Bh); cudaGetSymbolAddress((void**)&Bl, g_Bl);
    cudaGetSymbolAddress((void**)&Ch, g_Ch); cudaGetSymbolAddress((void**)&Cl, g_Cl);
    cudaGetSymbolAddress((void**)&Dh, g_Dh); cudaGetSymbolAddress((void**)&Dl, g_Dl);

    cudaFuncSetAttribute(gemm_mma<false>, cudaFuncAttributeMaxDynamicSharedMemorySize, GEMM_SMEM);
    cudaFuncSetAttribute(gemm_mma<true>,  cudaFuncAttributeMaxDynamicSharedMemorySize, GEMM_SMEM);

    // 0) split operands to bf16 hi/lo
    const int n4_u = (M * N_DIM) / 4;          // 4M
    const int n4_m = (N_DIM * N_DIM) / 4;      // 256K
    split_f32<<<(n4_u + 255) / 256, 256>>>((const float4*)u,  (uint2*)uh, (uint2*)ul, n4_u);
    split_f32<<<(n4_m + 255) / 256, 256>>>((const float4*)B,  (uint2*)Bh, (uint2*)Bl, n4_m);
    split_f32<<<(n4_m + 255) / 256, 256>>>((const float4*)C,  (uint2*)Ch, (uint2*)Cl, n4_m);
    split_f32<<<(n4_m + 255) / 256, 256>>>((const float4*)Dm, (uint2*)Dh, (uint2*)Dl, n4_m);

    dim3 grid(N_DIM / BN, M / BM);             // (8, 128)

    // 1) Bu = u @ B^T   (f32 out)
    gemm_mma<false><<<grid, 256, GEMM_SMEM>>>(uh, ul, Bh, Bl,
                                              nullptr, nullptr, nullptr, nullptr,
                                              Bu_p, M, N_DIM, N_DIM);

    // 2) in-place scan over T
    int p1_threads = batch * nChunks * N_DIM;
    scan_phase1<<<(p1_threads + 255) / 256, 256>>>(A, batch);
    scan_phase2<<<(batch * N_DIM + 255) / 256, 256>>>(A, batch);
    scan_phase3<<<(p1_threads + 255) / 256, 256>>>(A, batch);

    // 3) split X
    split_f32<<<(n4_u + 255) / 256, 256>>>((const float4*)Bu_p, (uint2*)Xh, (uint2*)Xl, n4_u);

    // 4) y = X @ C^T + u @ D^T   (dual accumulate)
    gemm_mma<true><<<grid, 256, GEMM_SMEM>>>(Xh, Xl, Ch, Cl,
                                             uh, ul, Dh, Dl,
                                             out, M, N_DIM, N_DIM);
}

// round 5
// speedup vs baseline: 2.3342x; 1.1328x over previous
#include <cuda_runtime.h>
#include <cuda_bf16.h>
#include <cstdint>

// Problem constants (fixed): u (8,2048,1024) f32, A/B/C/D (1024,1024) f32.
constexpr int N_DIM = 1024;
constexpr int T_LEN = 2048;
constexpr int CHUNK = 64;

// Scratch (__device__ globals; no allocation allowed).
__device__ float g_Bu[16777216];          // Bu local scans, f32 (64MB)
__device__ float g_carry[262144];
__device__ __nv_bfloat16 g_uh[16777216], g_ul[16777216];   // u hi/lo
__device__ __nv_bfloat16 g_Xh[16777216], g_Xl[16777216];   // X hi/lo
__device__ __nv_bfloat16 g_Bh[1048576],  g_Bl[1048576];
__device__ __nv_bfloat16 g_Ch[1048576],  g_Cl[1048576];
__device__ __nv_bfloat16 g_Dh[1048576],  g_Dl[1048576];

// ---------------------------------------------------------------------------
// helpers
// ---------------------------------------------------------------------------
__device__ __forceinline__ uint32_t smem_u32(const void* p) {
    uint32_t a;
    asm("{ .reg .u64 t; cvta.to.shared.u64 t, %1; cvt.u32.u64 %0, t; }" : "=r"(a) : "l"(p));
    return a;
}
__device__ __forceinline__ void cp_async16(uint32_t dst, const void* src) {
    asm volatile("cp.async.cg.shared.global [%0], [%1], 16;" :: "r"(dst), "l"(src));
}
__device__ __forceinline__ void cp_commit() {
    asm volatile("cp.async.commit_group;");
}
__device__ __forceinline__ void cp_wait1() {
    asm volatile("cp.async.wait_group 1;");
}
__device__ __forceinline__ void ldsm4(uint32_t* r, uint32_t addr) {
    asm volatile("ldmatrix.sync.aligned.m8n8.x4.shared.b16 {%0,%1,%2,%3}, [%4];"
                 : "=r"(r[0]), "=r"(r[1]), "=r"(r[2]), "=r"(r[3]) : "r"(addr));
}
__device__ __forceinline__ void mma16816(float* d, const uint32_t* a, const uint32_t* b) {
    asm volatile(
        "mma.sync.aligned.m16n8k16.row.col.f32.bf16.bf16.f32 "
        "{%0,%1,%2,%3}, {%4,%5,%6,%7}, {%8,%9}, {%0,%1,%2,%3};"
        : "+f"(d[0]), "+f"(d[1]), "+f"(d[2]), "+f"(d[3])
        : "r"(a[0]), "r"(a[1]), "r"(a[2]), "r"(a[3]), "r"(b[0]), "r"(b[1]));
}
__device__ __forceinline__ uint32_t pk_bf16(__nv_bfloat16 a, __nv_bfloat16 b) {
    return (uint32_t)__bfloat16_as_ushort(a) | ((uint32_t)__bfloat16_as_ushort(b) << 16);
}

// ---------------------------------------------------------------------------
// split f32 -> bf16 hi + bf16 lo (lo = bf16(x - f32(hi)))
// ---------------------------------------------------------------------------
__global__ void split_f32(const float4* __restrict__ src,
                          uint2* __restrict__ hi, uint2* __restrict__ lo, int n4)
{
    int i = blockIdx.x * blockDim.x + threadIdx.x;
    if (i >= n4) return;
    float4 v = src[i];
    __nv_bfloat16 h0 = __float2bfloat16(v.x), h1 = __float2bfloat16(v.y);
    __nv_bfloat16 h2 = __float2bfloat16(v.z), h3 = __float2bfloat16(v.w);
    __nv_bfloat16 l0 = __float2bfloat16(v.x - __bfloat162float(h0));
    __nv_bfloat16 l1 = __float2bfloat16(v.y - __bfloat162float(h1));
    __nv_bfloat16 l2 = __float2bfloat16(v.z - __bfloat162float(h2));
    __nv_bfloat16 l3 = __float2bfloat16(v.w - __bfloat162float(h3));
    hi[i] = make_uint2(pk_bf16(h0, h1), pk_bf16(h2, h3));
    lo[i] = make_uint2(pk_bf16(l0, l1), pk_bf16(l2, l3));
}

// ---------------------------------------------------------------------------
// bf16 3-product NT GEMM via mma.sync: out[m,n] = sum_k A[m,k]*B[n,k]
// (+ A2*B2 if DUAL).  A,B pre-split into hi/lo bf16 [*, K] row-major.
// 128x128x32 tiles, 256 threads (2x4 warps, 64x32 warp tile),
// 2-stage cp.async double buffer -> 80KB smem -> 2 CTAs/SM.
// A-frag registers are reused between the hi-A and lo-A phases to fit 128 regs.
// ---------------------------------------------------------------------------
constexpr int BM = 128, BN = 128, BK = 32;
constexpr int BKP = 40;                      // halves per row incl. 16B pad
constexpr int TILE_B = BM * BKP * 2;         // 10240 bytes per matrix tile
constexpr int STAGE_B = 4 * TILE_B;          // Ah, Al, Bh, Bl
constexpr int STAGES = 2;
constexpr int GEMM_SMEM = STAGES * STAGE_B;  // 81920

template <bool DUAL>
__global__ void __launch_bounds__(256, 2)
gemm_mma(const __nv_bfloat16* __restrict__ Ah, const __nv_bfloat16* __restrict__ Al,
         const __nv_bfloat16* __restrict__ Bh, const __nv_bfloat16* __restrict__ Bl,
         const __nv_bfloat16* __restrict__ A2h, const __nv_bfloat16* __restrict__ A2l,
         const __nv_bfloat16* __restrict__ B2h, const __nv_bfloat16* __restrict__ B2l,
         float* __restrict__ Cout, int M, int N, int K)
{
    extern __shared__ char smem[];
    const uint32_t sbase = smem_u32(smem);
    const int tid = threadIdx.x, lane = tid & 31, wid = tid >> 5;
    const int wm = wid >> 2, wn = wid & 3;
    const int m0 = blockIdx.y * BM, n0 = blockIdx.x * BN;

    const int IPER = K / BK;                  // 32
    const int KT = DUAL ? 2 * IPER : IPER;

    float acc[4][4][4] = {};

    auto issue = [&](int kt) {
        const bool p2 = DUAL && (kt >= IPER);
        const __nv_bfloat16* ah = p2 ? A2h : Ah;
        const __nv_bfloat16* al = p2 ? A2l : Al;
        const __nv_bfloat16* bh = p2 ? B2h : Bh;
        const __nv_bfloat16* bl = p2 ? B2l : Bl;
        const int k0 = (kt % IPER) * BK;
        const uint32_t st = sbase + (kt & 1) * STAGE_B;
        #pragma unroll
        for (int i = 0; i < 2; ++i) {
            const int cid = tid + i * 256;      // 0..511
            const int r = cid >> 2, c = cid & 3;
            const uint32_t dst = st + r * (BKP * 2) + c * 16;
            const size_t goA = (size_t)(m0 + r) * K + k0 + c * 8;
            const size_t goB = (size_t)(n0 + r) * K + k0 + c * 8;
            cp_async16(dst,              ah + goA);
            cp_async16(dst + TILE_B,     al + goA);
            cp_async16(dst + 2 * TILE_B, bh + goB);
            cp_async16(dst + 3 * TILE_B, bl + goB);
        }
    };

    issue(0); cp_commit();
    issue(1); cp_commit();

    // per-lane ldmatrix address bases (byte offsets within a tile)
    const uint32_t a_base = (((wm * 64 + (lane & 15)) * BKP) + ((lane >> 4) << 3)) * 2;
    const uint32_t b_base = (((wn * 32 + (lane & 7) + ((lane >> 4) << 3)) * BKP) +
                             (((lane >> 3) & 1) << 3)) * 2;

    for (int kt = 0; kt < KT; ++kt) {
        cp_wait1();                 // stage (kt&1) is resident
        __syncthreads();

        const uint32_t st = sbase + (kt & 1) * STAGE_B;
        const uint32_t sAh = st, sAl = st + TILE_B, sBh = st + 2 * TILE_B, sBl = st + 3 * TILE_B;

        #pragma unroll
        for (int k16 = 0; k16 < 2; ++k16) {
            uint32_t afr[4][4], bhr[2][4], blr[2][4];
            #pragma unroll
            for (int nj = 0; nj < 2; ++nj) {
                const uint32_t off = b_base + nj * (16 * BKP * 2) + k16 * 32;
                ldsm4(bhr[nj], sBh + off);
                ldsm4(blr[nj], sBl + off);
            }
            // phase 1: A-hi frags -> hi*hi and hi*lo
            #pragma unroll
            for (int mi = 0; mi < 4; ++mi)
                ldsm4(afr[mi], sAh + a_base + mi * (16 * BKP * 2) + k16 * 32);
            #pragma unroll
            for (int mi = 0; mi < 4; ++mi) {
                #pragma unroll
                for (int nf = 0; nf < 4; ++nf) {
                    mma16816(acc[mi][nf], afr[mi], &bhr[nf >> 1][(nf & 1) * 2]);
                    mma16816(acc[mi][nf], afr[mi], &blr[nf >> 1][(nf & 1) * 2]);
                }
            }
            // phase 2: reload same regs with A-lo -> lo*hi
            #pragma unroll
            for (int mi = 0; mi < 4; ++mi)
                ldsm4(afr[mi], sAl + a_base + mi * (16 * BKP * 2) + k16 * 32);
            #pragma unroll
            for (int mi = 0; mi < 4; ++mi)
                #pragma unroll
                for (int nf = 0; nf < 4; ++nf)
                    mma16816(acc[mi][nf], afr[mi], &bhr[nf >> 1][(nf & 1) * 2]);
        }

        __syncthreads();            // everyone done reading stage (kt&1)
        if (kt + 2 < KT) issue(kt + 2);
        cp_commit();
    }

    // epilogue: d-frag m16n8: d0,d1 -> (row, col..col+1); d2,d3 -> row+8
    #pragma unroll
    for (int mi = 0; mi < 4; ++mi) {
        const int row0 = m0 + wm * 64 + mi * 16 + (lane >> 2);
        #pragma unroll
        for (int nf = 0; nf < 4; ++nf) {
            const int col = n0 + wn * 32 + (nf >> 1) * 16 + (nf & 1) * 8 + (lane & 3) * 2;
            *(float2*)&Cout[(size_t)row0 * N + col] =
                make_float2(acc[mi][nf][0], acc[mi][nf][1]);
            *(float2*)&Cout[(size_t)(row0 + 8) * N + col] =
                make_float2(acc[mi][nf][2], acc[mi][nf][3]);
        }
    }
}

// ---------------------------------------------------------------------------
// Chunked parallel scan over T on g_Bu:  x_t = a * x_{t-1} + Bu_t
// phase3 fuses the carry fix-up with the bf16 hi/lo split of X.
// ---------------------------------------------------------------------------
__global__ void scan_phase1(const float* __restrict__ Afull, int batch)
{
    const int nChunks = T_LEN / CHUNK;
    int id = blockIdx.x * blockDim.x + threadIdx.x;
    int n  = id & (N_DIM - 1);
    int bc = id >> 10;
    if (bc >= batch * nChunks) return;
    int c = bc % nChunks, b = bc / nChunks;

    const float a = Afull[(size_t)n * N_DIM + n];
    size_t base = ((size_t)(b * T_LEN + c * CHUNK)) * N_DIM + n;

    float x = 0.0f;
    #pragma unroll 8
    for (int t = 0; t < CHUNK; ++t) {
        float v = g_Bu[base + (size_t)t * N_DIM];
        x = fmaf(x, a, v);
        g_Bu[base + (size_t)t * N_DIM] = x;
    }
    g_carry[(size_t)bc * N_DIM + n] = x;
}

__global__ void scan_phase2(const float* __restrict__ Afull, int batch)
{
    const int nChunks = T_LEN / CHUNK;
    int id = blockIdx.x * blockDim.x + threadIdx.x;
    if (id >= batch * N_DIM) return;
    int n = id & (N_DIM - 1), b = id >> 10;

    float a  = Afull[(size_t)n * N_DIM + n];
    float aC = a;
    #pragma unroll
    for (int i = 0; i < 6; ++i) aC *= aC;

    float S = 0.0f;
    for (int c = 0; c < nChunks; ++c) {
        size_t idx = (size_t)(b * nChunks + c) * N_DIM + n;
        float L = g_carry[idx];
        g_carry[idx] = S;
        S = fmaf(aC, S, L);
    }
}

// phase3: X = local + a^{t+1} * carry, written directly as bf16 hi/lo.
__global__ void scan_phase3(const float* __restrict__ Afull, int batch)
{
    const int nChunks = T_LEN / CHUNK;
    int id = blockIdx.x * blockDim.x + threadIdx.x;
    int n  = id & (N_DIM - 1);
    int bc = id >> 10;
    if (bc >= batch * nChunks) return;
    int c = bc % nChunks, b = bc / nChunks;

    const float S = g_carry[(size_t)bc * N_DIM + n];
    const float a = Afull[(size_t)n * N_DIM + n];
    size_t base = ((size_t)(b * T_LEN + c * CHUNK)) * N_DIM + n;

    float f = a;
    #pragma unroll 8
    for (int t = 0; t < CHUNK; ++t) {
        size_t idx = base + (size_t)t * N_DIM;
        float x = fmaf(f, S, g_Bu[idx]);
        f *= a;
        __nv_bfloat16 h = __float2bfloat16(x);
        __nv_bfloat16 l = __float2bfloat16(x - __bfloat162float(h));
        g_Xh[idx] = h;
        g_Xl[idx] = l;
    }
}

// ---------------------------------------------------------------------------
extern "C" void kernel_launch(void* const* d_in, const int* in_sizes, int n_in,
                              void* d_out, int out_size)
{
    const float* u  = (const float*)d_in[0];   // (batch, T, m)
    const float* A  = (const float*)d_in[1];   // (n, n)
    const float* B  = (const float*)d_in[2];   // (n, m)
    const float* C  = (const float*)d_in[3];   // (p, n)
    const float* Dm = (const float*)d_in[4];   // (p, m)
    float* out = (float*)d_out;

    const int M     = in_sizes[0] / N_DIM;     // 16384
    const int batch = M / T_LEN;               // 8
    const int nChunks = T_LEN / CHUNK;

    float *Bu_p; cudaGetSymbolAddress((void**)&Bu_p, g_Bu);
    __nv_bfloat16 *uh, *ul, *Xh, *Xl, *Bh, *Bl, *Ch, *Cl, *Dh, *Dl;
    cudaGetSymbolAddress((void**)&uh, g_uh); cudaGetSymbolAddress((void**)&ul, g_ul);
    cudaGetSymbolAddress((void**)&Xh, g_Xh); cudaGetSymbolAddress((void**)&Xl, g_Xl);
    cudaGetSymbolAddress((void**)&Bh, g_Bh); cudaGetSymbolAddress((void**)&Bl, g_Bl);
    cudaGetSymbolAddress((void**)&Ch, g_Ch); cudaGetSymbolAddress((void**)&Cl, g_Cl);
    cudaGetSymbolAddress((void**)&Dh, g_Dh); cudaGetSymbolAddress((void**)&Dl, g_Dl);

    cudaFuncSetAttribute(gemm_mma<false>, cudaFuncAttributeMaxDynamicSharedMemorySize, GEMM_SMEM);
    cudaFuncSetAttribute(gemm_mma<true>,  cudaFuncAttributeMaxDynamicSharedMemorySize, GEMM_SMEM);

    // 0) split operands to bf16 hi/lo
    const int n4_u = (M * N_DIM) / 4;          // 4M
    const int n4_m = (N_DIM * N_DIM) / 4;      // 256K
    split_f32<<<(n4_u + 255) / 256, 256>>>((const float4*)u,  (uint2*)uh, (uint2*)ul, n4_u);
    split_f32<<<(n4_m + 255) / 256, 256>>>((const float4*)B,  (uint2*)Bh, (uint2*)Bl, n4_m);
    split_f32<<<(n4_m + 255) / 256, 256>>>((const float4*)C,  (uint2*)Ch, (uint2*)Cl, n4_m);
    split_f32<<<(n4_m + 255) / 256, 256>>>((const float4*)Dm, (uint2*)Dh, (uint2*)Dl, n4_m);

    dim3 grid(N_DIM / BN, M / BM);             // (8, 128)

    // 1) Bu = u @ B^T   (f32 out)
    gemm_mma<false><<<grid, 256, GEMM_SMEM>>>(uh, ul, Bh, Bl,
                                              nullptr, nullptr, nullptr, nullptr,
                                              Bu_p, M, N_DIM, N_DIM);

    // 2) scan over T; phase3 emits X directly as bf16 hi/lo
    int p1_threads = batch * nChunks * N_DIM;
    scan_phase1<<<(p1_threads + 255) / 256, 256>>>(A, batch);
    scan_phase2<<<(batch * N_DIM + 255) / 256, 256>>>(A, batch);
    scan_phase3<<<(p1_threads + 255) / 256, 256>>>(A, batch);

    // 3) y = X @ C^T + u @ D^T   (dual accumulate)
    gemm_mma<true><<<grid, 256, GEMM_SMEM>>>(Xh, Xl, Ch, Cl,
                                             uh, ul, Dh, Dl,
                                             out, M, N_DIM, N_DIM);
}

// round 6
// speedup vs baseline: 3.3536x; 1.4367x over previous
#include <cuda_runtime.h>
#include <cuda_fp16.h>
#include <cstdint>

// Problem constants (fixed): u (8,2048,1024) f32, A/B/C/D (1024,1024) f32.
constexpr int N_DIM = 1024;
constexpr int T_LEN = 2048;
constexpr int CHUNK = 64;

// Scratch (__device__ globals; no allocation allowed).
__device__ float g_Bu[16777216];          // Bu local scans, f32 (64MB)
__device__ float g_carry[262144];
__device__ __half g_uh[16777216];                       // u hi (fp16)
__device__ __half g_Xh[16777216];                       // X hi (fp16)
__device__ __half g_Bh[1048576], g_Bl[1048576];
__device__ __half g_Ch[1048576], g_Cl[1048576];
__device__ __half g_Dh[1048576], g_Dl[1048576];

// ---------------------------------------------------------------------------
// helpers
// ---------------------------------------------------------------------------
__device__ __forceinline__ uint32_t smem_u32(const void* p) {
    uint32_t a;
    asm("{ .reg .u64 t; cvta.to.shared.u64 t, %1; cvt.u32.u64 %0, t; }" : "=r"(a) : "l"(p));
    return a;
}
__device__ __forceinline__ void cp_async16(uint32_t dst, const void* src) {
    asm volatile("cp.async.cg.shared.global [%0], [%1], 16;" :: "r"(dst), "l"(src));
}
__device__ __forceinline__ void cp_commit() {
    asm volatile("cp.async.commit_group;");
}
__device__ __forceinline__ void cp_wait1() {
    asm volatile("cp.async.wait_group 1;");
}
__device__ __forceinline__ void ldsm4(uint32_t* r, uint32_t addr) {
    asm volatile("ldmatrix.sync.aligned.m8n8.x4.shared.b16 {%0,%1,%2,%3}, [%4];"
                 : "=r"(r[0]), "=r"(r[1]), "=r"(r[2]), "=r"(r[3]) : "r"(addr));
}
__device__ __forceinline__ void mma16816(float* d, const uint32_t* a, const uint32_t* b) {
    asm volatile(
        "mma.sync.aligned.m16n8k16.row.col.f32.f16.f16.f32 "
        "{%0,%1,%2,%3}, {%4,%5,%6,%7}, {%8,%9}, {%0,%1,%2,%3};"
        : "+f"(d[0]), "+f"(d[1]), "+f"(d[2]), "+f"(d[3])
        : "r"(a[0]), "r"(a[1]), "r"(a[2]), "r"(a[3]), "r"(b[0]), "r"(b[1]));
}
__device__ __forceinline__ uint32_t pk_f16(__half a, __half b) {
    return (uint32_t)__half_as_ushort(a) | ((uint32_t)__half_as_ushort(b) << 16);
}

// ---------------------------------------------------------------------------
// split f32 -> f16 hi + f16 lo (lo = f16(x - f32(hi)))
// ---------------------------------------------------------------------------
__global__ void split_f32_hl(const float4* __restrict__ src,
                             uint2* __restrict__ hi, uint2* __restrict__ lo, int n4)
{
    int i = blockIdx.x * blockDim.x + threadIdx.x;
    if (i >= n4) return;
    float4 v = src[i];
    __half h0 = __float2half(v.x), h1 = __float2half(v.y);
    __half h2 = __float2half(v.z), h3 = __float2half(v.w);
    __half l0 = __float2half(v.x - __half2float(h0));
    __half l1 = __float2half(v.y - __half2float(h1));
    __half l2 = __float2half(v.z - __half2float(h2));
    __half l3 = __float2half(v.w - __half2float(h3));
    hi[i] = make_uint2(pk_f16(h0, h1), pk_f16(h2, h3));
    lo[i] = make_uint2(pk_f16(l0, l1), pk_f16(l2, l3));
}

__global__ void split_f32_hi(const float4* __restrict__ src,
                             uint2* __restrict__ hi, int n4)
{
    int i = blockIdx.x * blockDim.x + threadIdx.x;
    if (i >= n4) return;
    float4 v = src[i];
    hi[i] = make_uint2(pk_f16(__float2half(v.x), __float2half(v.y)),
                       pk_f16(__float2half(v.z), __float2half(v.w)));
}

// ---------------------------------------------------------------------------
// fp16 2-product NT GEMM via mma.sync: out[m,n] = sum_k A[m,k]*B[n,k]
// (+ A2*B2 if DUAL).  A in fp16-hi only; B pre-split into hi/lo.
// a*b ~= ah*bh + ah*bl  (drops al*b, ~1.4e-4 relative).
// 128x128x32 tiles, 256 threads (2x4 warps, 64x32 warp tile),
// 3-stage cp.async pipeline, 2 CTAs/SM (92KB smem each).
// ---------------------------------------------------------------------------
constexpr int BM = 128, BN = 128, BK = 32;
constexpr int BKP = 40;                      // halves per row incl. 16B pad
constexpr int TILE_B = BM * BKP * 2;         // 10240 bytes per matrix tile
constexpr int STAGE_B = 3 * TILE_B;          // Ah, Bh, Bl
constexpr int STAGES = 3;
constexpr int GEMM_SMEM = STAGES * STAGE_B;  // 92160

template <bool DUAL>
__global__ void __launch_bounds__(256, 2)
gemm_mma(const __half* __restrict__ Ah,
         const __half* __restrict__ Bh, const __half* __restrict__ Bl,
         const __half* __restrict__ A2h,
         const __half* __restrict__ B2h, const __half* __restrict__ B2l,
         float* __restrict__ Cout, int M, int N, int K)
{
    extern __shared__ char smem[];
    const uint32_t sbase = smem_u32(smem);
    const int tid = threadIdx.x, lane = tid & 31, wid = tid >> 5;
    const int wm = wid >> 2, wn = wid & 3;
    const int m0 = blockIdx.y * BM, n0 = blockIdx.x * BN;

    const int IPER = K / BK;                  // 32
    const int KT = DUAL ? 2 * IPER : IPER;

    float acc[4][4][4] = {};

    auto issue = [&](int kt) {
        const bool p2 = DUAL && (kt >= IPER);
        const __half* ah = p2 ? A2h : Ah;
        const __half* bh = p2 ? B2h : Bh;
        const __half* bl = p2 ? B2l : Bl;
        const int k0 = (kt % IPER) * BK;
        const uint32_t st = sbase + (kt % STAGES) * STAGE_B;
        #pragma unroll
        for (int i = 0; i < 2; ++i) {
            const int cid = tid + i * 256;      // 0..511
            const int r = cid >> 2, c = cid & 3;
            const uint32_t dst = st + r * (BKP * 2) + c * 16;
            const size_t goA = (size_t)(m0 + r) * K + k0 + c * 8;
            const size_t goB = (size_t)(n0 + r) * K + k0 + c * 8;
            cp_async16(dst,              ah + goA);
            cp_async16(dst + TILE_B,     bh + goB);
            cp_async16(dst + 2 * TILE_B, bl + goB);
        }
    };

    issue(0); cp_commit();
    issue(1); cp_commit();

    // per-lane ldmatrix address bases (byte offsets within a tile)
    const uint32_t a_base = (((wm * 64 + (lane & 15)) * BKP) + ((lane >> 4) << 3)) * 2;
    const uint32_t b_base = (((wn * 32 + (lane & 7) + ((lane >> 4) << 3)) * BKP) +
                             (((lane >> 3) & 1) << 3)) * 2;

    for (int kt = 0; kt < KT; ++kt) {
        cp_wait1();                 // stage kt%3 resident; kt+1 still pending
        __syncthreads();            // also: all warps done reading stage (kt+2)%3
        if (kt + 2 < KT) issue(kt + 2);
        cp_commit();

        const uint32_t st = sbase + (kt % STAGES) * STAGE_B;
        const uint32_t sAh = st, sBh = st + TILE_B, sBl = st + 2 * TILE_B;

        #pragma unroll
        for (int k16 = 0; k16 < 2; ++k16) {
            uint32_t afr[4][4], bhr[2][4], blr[2][4];
            #pragma unroll
            for (int nj = 0; nj < 2; ++nj) {
                const uint32_t off = b_base + nj * (16 * BKP * 2) + k16 * 32;
                ldsm4(bhr[nj], sBh + off);
                ldsm4(blr[nj], sBl + off);
            }
            #pragma unroll
            for (int mi = 0; mi < 4; ++mi)
                ldsm4(afr[mi], sAh + a_base + mi * (16 * BKP * 2) + k16 * 32);
            #pragma unroll
            for (int mi = 0; mi < 4; ++mi) {
                #pragma unroll
                for (int nf = 0; nf < 4; ++nf) {
                    mma16816(acc[mi][nf], afr[mi], &bhr[nf >> 1][(nf & 1) * 2]);
                    mma16816(acc[mi][nf], afr[mi], &blr[nf >> 1][(nf & 1) * 2]);
                }
            }
        }
    }

    // epilogue: d-frag m16n8: d0,d1 -> (row, col..col+1); d2,d3 -> row+8
    #pragma unroll
    for (int mi = 0; mi < 4; ++mi) {
        const int row0 = m0 + wm * 64 + mi * 16 + (lane >> 2);
        #pragma unroll
        for (int nf = 0; nf < 4; ++nf) {
            const int col = n0 + wn * 32 + (nf >> 1) * 16 + (nf & 1) * 8 + (lane & 3) * 2;
            *(float2*)&Cout[(size_t)row0 * N + col] =
                make_float2(acc[mi][nf][0], acc[mi][nf][1]);
            *(float2*)&Cout[(size_t)(row0 + 8) * N + col] =
                make_float2(acc[mi][nf][2], acc[mi][nf][3]);
        }
    }
}

// ---------------------------------------------------------------------------
// Chunked parallel scan over T on g_Bu:  x_t = a * x_{t-1} + Bu_t
// phase3 fuses the carry fix-up with the fp16 conversion of X.
// ---------------------------------------------------------------------------
__global__ void scan_phase1(const float* __restrict__ Afull, int batch)
{
    const int nChunks = T_LEN / CHUNK;
    int id = blockIdx.x * blockDim.x + threadIdx.x;
    int n  = id & (N_DIM - 1);
    int bc = id >> 10;
    if (bc >= batch * nChunks) return;
    int c = bc % nChunks, b = bc / nChunks;

    const float a = Afull[(size_t)n * N_DIM + n];
    size_t base = ((size_t)(b * T_LEN + c * CHUNK)) * N_DIM + n;

    float x = 0.0f;
    #pragma unroll 8
    for (int t = 0; t < CHUNK; ++t) {
        float v = g_Bu[base + (size_t)t * N_DIM];
        x = fmaf(x, a, v);
        g_Bu[base + (size_t)t * N_DIM] = x;
    }
    g_carry[(size_t)bc * N_DIM + n] = x;
}

__global__ void scan_phase2(const float* __restrict__ Afull, int batch)
{
    const int nChunks = T_LEN / CHUNK;
    int id = blockIdx.x * blockDim.x + threadIdx.x;
    if (id >= batch * N_DIM) return;
    int n = id & (N_DIM - 1), b = id >> 10;

    float a  = Afull[(size_t)n * N_DIM + n];
    float aC = a;
    #pragma unroll
    for (int i = 0; i < 6; ++i) aC *= aC;

    float S = 0.0f;
    for (int c = 0; c < nChunks; ++c) {
        size_t idx = (size_t)(b * nChunks + c) * N_DIM + n;
        float L = g_carry[idx];
        g_carry[idx] = S;
        S = fmaf(aC, S, L);
    }
}

// phase3: X = local + a^{t+1} * carry, written directly as fp16 hi.
__global__ void scan_phase3(const float* __restrict__ Afull, int batch)
{
    const int nChunks = T_LEN / CHUNK;
    int id = blockIdx.x * blockDim.x + threadIdx.x;
    int n  = id & (N_DIM - 1);
    int bc = id >> 10;
    if (bc >= batch * nChunks) return;
    int c = bc % nChunks, b = bc / nChunks;

    const float S = g_carry[(size_t)bc * N_DIM + n];
    const float a = Afull[(size_t)n * N_DIM + n];
    size_t base = ((size_t)(b * T_LEN + c * CHUNK)) * N_DIM + n;

    float f = a;
    #pragma unroll 8
    for (int t = 0; t < CHUNK; ++t) {
        size_t idx = base + (size_t)t * N_DIM;
        float x = fmaf(f, S, g_Bu[idx]);
        f *= a;
        g_Xh[idx] = __float2half(x);
    }
}

// ---------------------------------------------------------------------------
extern "C" void kernel_launch(void* const* d_in, const int* in_sizes, int n_in,
                              void* d_out, int out_size)
{
    const float* u  = (const float*)d_in[0];   // (batch, T, m)
    const float* A  = (const float*)d_in[1];   // (n, n)
    const float* B  = (const float*)d_in[2];   // (n, m)
    const float* C  = (const float*)d_in[3];   // (p, n)
    const float* Dm = (const float*)d_in[4];   // (p, m)
    float* out = (float*)d_out;

    const int M     = in_sizes[0] / N_DIM;     // 16384
    const int batch = M / T_LEN;               // 8
    const int nChunks = T_LEN / CHUNK;

    float *Bu_p; cudaGetSymbolAddress((void**)&Bu_p, g_Bu);
    __half *uh, *Xh, *Bh, *Bl, *Ch, *Cl, *Dh, *Dl;
    cudaGetSymbolAddress((void**)&uh, g_uh);
    cudaGetSymbolAddress((void**)&Xh, g_Xh);
    cudaGetSymbolAddress((void**)&Bh, g_Bh); cudaGetSymbolAddress((void**)&Bl, g_Bl);
    cudaGetSymbolAddress((void**)&Ch, g_Ch); cudaGetSymbolAddress((void**)&Cl, g_Cl);
    cudaGetSymbolAddress((void**)&Dh, g_Dh); cudaGetSymbolAddress((void**)&Dl, g_Dl);

    cudaFuncSetAttribute(gemm_mma<false>, cudaFuncAttributeMaxDynamicSharedMemorySize, GEMM_SMEM);
    cudaFuncSetAttribute(gemm_mma<true>,  cudaFuncAttributeMaxDynamicSharedMemorySize, GEMM_SMEM);

    // 0) split operands (u: hi only; B/C/D: hi+lo)
    const int n4_u = (M * N_DIM) / 4;          // 4M
    const int n4_m = (N_DIM * N_DIM) / 4;      // 256K
    split_f32_hi<<<(n4_u + 255) / 256, 256>>>((const float4*)u,  (uint2*)uh, n4_u);
    split_f32_hl<<<(n4_m + 255) / 256, 256>>>((const float4*)B,  (uint2*)Bh, (uint2*)Bl, n4_m);
    split_f32_hl<<<(n4_m + 255) / 256, 256>>>((const float4*)C,  (uint2*)Ch, (uint2*)Cl, n4_m);
    split_f32_hl<<<(n4_m + 255) / 256, 256>>>((const float4*)Dm, (uint2*)Dh, (uint2*)Dl, n4_m);

    dim3 grid(N_DIM / BN, M / BM);             // (8, 128)

    // 1) Bu = u @ B^T   (f32 out)
    gemm_mma<false><<<grid, 256, GEMM_SMEM>>>(uh, Bh, Bl,
                                              nullptr, nullptr, nullptr,
                                              Bu_p, M, N_DIM, N_DIM);

    // 2) scan over T; phase3 emits X directly as fp16
    int p1_threads = batch * nChunks * N_DIM;
    scan_phase1<<<(p1_threads + 255) / 256, 256>>>(A, batch);
    scan_phase2<<<(batch * N_DIM + 255) / 256, 256>>>(A, batch);
    scan_phase3<<<(p1_threads + 255) / 256, 256>>>(A, batch);

    // 3) y = X @ C^T + u @ D^T   (dual accumulate)
    gemm_mma<true><<<grid, 256, GEMM_SMEM>>>(Xh, Ch, Cl,
                                             uh, Dh, Dl,
                                             out, M, N_DIM, N_DIM);
}

// round 7
// speedup vs baseline: 5.3201x; 1.5864x over previous
#include <cuda_runtime.h>
#include <cuda_fp16.h>
#include <cstdint>

// Problem constants (fixed): u (8,2048,1024) f32, A/B/C/D (1024,1024) f32.
constexpr int N_DIM = 1024;
constexpr int T_LEN = 2048;
constexpr int CHUNK = 64;

// Scratch (__device__ globals; no allocation allowed).
__device__ float g_Bu[16777216];          // Bu local scans, f32 (64MB)
__device__ float g_carry[262144];
__device__ __half g_uh[16777216];         // u  (fp16)
__device__ __half g_Xh[16777216];         // X  (fp16)
__device__ __half g_Bh[1048576];
__device__ __half g_Ch[1048576];
__device__ __half g_Dh[1048576];

// ---------------------------------------------------------------------------
// helpers
// ---------------------------------------------------------------------------
__device__ __forceinline__ uint32_t smem_u32(const void* p) {
    uint32_t a;
    asm("{ .reg .u64 t; cvta.to.shared.u64 t, %1; cvt.u32.u64 %0, t; }" : "=r"(a) : "l"(p));
    return a;
}
__device__ __forceinline__ void cp_async16(uint32_t dst, const void* src) {
    asm volatile("cp.async.cg.shared.global [%0], [%1], 16;" :: "r"(dst), "l"(src));
}
__device__ __forceinline__ void cp_commit() {
    asm volatile("cp.async.commit_group;");
}
__device__ __forceinline__ void cp_wait2() {
    asm volatile("cp.async.wait_group 2;");
}
__device__ __forceinline__ void ldsm4(uint32_t* r, uint32_t addr) {
    asm volatile("ldmatrix.sync.aligned.m8n8.x4.shared.b16 {%0,%1,%2,%3}, [%4];"
                 : "=r"(r[0]), "=r"(r[1]), "=r"(r[2]), "=r"(r[3]) : "r"(addr));
}
__device__ __forceinline__ void mma16816(float* d, const uint32_t* a, const uint32_t* b) {
    asm volatile(
        "mma.sync.aligned.m16n8k16.row.col.f32.f16.f16.f32 "
        "{%0,%1,%2,%3}, {%4,%5,%6,%7}, {%8,%9}, {%0,%1,%2,%3};"
        : "+f"(d[0]), "+f"(d[1]), "+f"(d[2]), "+f"(d[3])
        : "r"(a[0]), "r"(a[1]), "r"(a[2]), "r"(a[3]), "r"(b[0]), "r"(b[1]));
}
__device__ __forceinline__ uint32_t pk_f16(__half a, __half b) {
    return (uint32_t)__half_as_ushort(a) | ((uint32_t)__half_as_ushort(b) << 16);
}

// ---------------------------------------------------------------------------
// convert f32 -> f16
// ---------------------------------------------------------------------------
__global__ void split_f32_hi(const float4* __restrict__ src,
                             uint2* __restrict__ hi, int n4)
{
    int i = blockIdx.x * blockDim.x + threadIdx.x;
    if (i >= n4) return;
    float4 v = src[i];
    hi[i] = make_uint2(pk_f16(__float2half(v.x), __float2half(v.y)),
                       pk_f16(__float2half(v.z), __float2half(v.w)));
}

// ---------------------------------------------------------------------------
// fp16 NT GEMM via mma.sync: out[m,n] = sum_k A[m,k]*B[n,k] (+ A2*B2 if DUAL)
// 128x128x32 tiles, 256 threads (2x4 warps, 64x32 warp tile),
// 4-stage cp.async pipeline (20KB/stage), 2 CTAs/SM, 1 syncthreads/iter.
// ---------------------------------------------------------------------------
constexpr int BM = 128, BN = 128, BK = 32;
constexpr int BKP = 40;                      // halves per row incl. 16B pad
constexpr int TILE_B = BM * BKP * 2;         // 10240 bytes per matrix tile
constexpr int STAGE_B = 2 * TILE_B;          // Ah, Bh
constexpr int STAGES = 4;
constexpr int GEMM_SMEM = STAGES * STAGE_B;  // 81920

template <bool DUAL>
__global__ void __launch_bounds__(256, 2)
gemm_mma(const __half* __restrict__ Ah, const __half* __restrict__ Bh,
         const __half* __restrict__ A2h, const __half* __restrict__ B2h,
         float* __restrict__ Cout, int M, int N, int K)
{
    extern __shared__ char smem[];
    const uint32_t sbase = smem_u32(smem);
    const int tid = threadIdx.x, lane = tid & 31, wid = tid >> 5;
    const int wm = wid >> 2, wn = wid & 3;
    const int m0 = blockIdx.y * BM, n0 = blockIdx.x * BN;

    const int IPER = K / BK;                  // 32
    const int KT = DUAL ? 2 * IPER : IPER;

    float acc[4][4][4] = {};

    auto issue = [&](int kt) {
        const bool p2 = DUAL && (kt >= IPER);
        const __half* ah = p2 ? A2h : Ah;
        const __half* bh = p2 ? B2h : Bh;
        const int k0 = (kt % IPER) * BK;
        const uint32_t st = sbase + (kt % STAGES) * STAGE_B;
        #pragma unroll
        for (int i = 0; i < 2; ++i) {
            const int cid = tid + i * 256;      // 0..511
            const int r = cid >> 2, c = cid & 3;
            const uint32_t dst = st + r * (BKP * 2) + c * 16;
            cp_async16(dst,          ah + (size_t)(m0 + r) * K + k0 + c * 8);
            cp_async16(dst + TILE_B, bh + (size_t)(n0 + r) * K + k0 + c * 8);
        }
    };

    issue(0); cp_commit();
    issue(1); cp_commit();
    issue(2); cp_commit();

    // per-lane ldmatrix address bases (byte offsets within a tile)
    const uint32_t a_base = (((wm * 64 + (lane & 15)) * BKP) + ((lane >> 4) << 3)) * 2;
    const uint32_t b_base = (((wn * 32 + (lane & 7) + ((lane >> 4) << 3)) * BKP) +
                             (((lane >> 3) & 1) << 3)) * 2;

    for (int kt = 0; kt < KT; ++kt) {
        cp_wait2();                 // stage kt%4 resident for this thread
        __syncthreads();            // all threads' copies visible; prev compute done
        if (kt + 3 < KT) { issue(kt + 3); }
        cp_commit();

        const uint32_t st = sbase + (kt % STAGES) * STAGE_B;
        const uint32_t sAh = st, sBh = st + TILE_B;

        #pragma unroll
        for (int k16 = 0; k16 < 2; ++k16) {
            uint32_t afr[4][4], bfr[2][4];
            #pragma unroll
            for (int nj = 0; nj < 2; ++nj)
                ldsm4(bfr[nj], sBh + b_base + nj * (16 * BKP * 2) + k16 * 32);
            #pragma unroll
            for (int mi = 0; mi < 4; ++mi)
                ldsm4(afr[mi], sAh + a_base + mi * (16 * BKP * 2) + k16 * 32);
            #pragma unroll
            for (int mi = 0; mi < 4; ++mi)
                #pragma unroll
                for (int nf = 0; nf < 4; ++nf)
                    mma16816(acc[mi][nf], afr[mi], &bfr[nf >> 1][(nf & 1) * 2]);
        }
    }

    // epilogue: d-frag m16n8: d0,d1 -> (row, col..col+1); d2,d3 -> row+8
    #pragma unroll
    for (int mi = 0; mi < 4; ++mi) {
        const int row0 = m0 + wm * 64 + mi * 16 + (lane >> 2);
        #pragma unroll
        for (int nf = 0; nf < 4; ++nf) {
            const int col = n0 + wn * 32 + (nf >> 1) * 16 + (nf & 1) * 8 + (lane & 3) * 2;
            *(float2*)&Cout[(size_t)row0 * N + col] =
                make_float2(acc[mi][nf][0], acc[mi][nf][1]);
            *(float2*)&Cout[(size_t)(row0 + 8) * N + col] =
                make_float2(acc[mi][nf][2], acc[mi][nf][3]);
        }
    }
}

// ---------------------------------------------------------------------------
// Chunked parallel scan over T on g_Bu:  x_t = a * x_{t-1} + Bu_t
// phase3 fuses the carry fix-up with the fp16 conversion of X.
// ---------------------------------------------------------------------------
__global__ void scan_phase1(const float* __restrict__ Afull, int batch)
{
    const int nChunks = T_LEN / CHUNK;
    int id = blockIdx.x * blockDim.x + threadIdx.x;
    int n  = id & (N_DIM - 1);
    int bc = id >> 10;
    if (bc >= batch * nChunks) return;
    int c = bc % nChunks, b = bc / nChunks;

    const float a = Afull[(size_t)n * N_DIM + n];
    size_t base = ((size_t)(b * T_LEN + c * CHUNK)) * N_DIM + n;

    float x = 0.0f;
    #pragma unroll 8
    for (int t = 0; t < CHUNK; ++t) {
        float v = g_Bu[base + (size_t)t * N_DIM];
        x = fmaf(x, a, v);
        g_Bu[base + (size_t)t * N_DIM] = x;
    }
    g_carry[(size_t)bc * N_DIM + n] = x;
}

__global__ void scan_phase2(const float* __restrict__ Afull, int batch)
{
    const int nChunks = T_LEN / CHUNK;
    int id = blockIdx.x * blockDim.x + threadIdx.x;
    if (id >= batch * N_DIM) return;
    int n = id & (N_DIM - 1), b = id >> 10;

    float a  = Afull[(size_t)n * N_DIM + n];
    float aC = a;
    #pragma unroll
    for (int i = 0; i < 6; ++i) aC *= aC;

    float S = 0.0f;
    for (int c = 0; c < nChunks; ++c) {
        size_t idx = (size_t)(b * nChunks + c) * N_DIM + n;
        float L = g_carry[idx];
        g_carry[idx] = S;
        S = fmaf(aC, S, L);
    }
}

// phase3: X = local + a^{t+1} * carry, written directly as fp16.
__global__ void scan_phase3(const float* __restrict__ Afull, int batch)
{
    const int nChunks = T_LEN / CHUNK;
    int id = blockIdx.x * blockDim.x + threadIdx.x;
    int n  = id & (N_DIM - 1);
    int bc = id >> 10;
    if (bc >= batch * nChunks) return;
    int c = bc % nChunks, b = bc / nChunks;

    const float S = g_carry[(size_t)bc * N_DIM + n];
    const float a = Afull[(size_t)n * N_DIM + n];
    size_t base = ((size_t)(b * T_LEN + c * CHUNK)) * N_DIM + n;

    float f = a;
    #pragma unroll 8
    for (int t = 0; t < CHUNK; ++t) {
        size_t idx = base + (size_t)t * N_DIM;
        float x = fmaf(f, S, g_Bu[idx]);
        f *= a;
        g_Xh[idx] = __float2half(x);
    }
}

// ---------------------------------------------------------------------------
extern "C" void kernel_launch(void* const* d_in, const int* in_sizes, int n_in,
                              void* d_out, int out_size)
{
    const float* u  = (const float*)d_in[0];   // (batch, T, m)
    const float* A  = (const float*)d_in[1];   // (n, n)
    const float* B  = (const float*)d_in[2];   // (n, m)
    const float* C  = (const float*)d_in[3];   // (p, n)
    const float* Dm = (const float*)d_in[4];   // (p, m)
    float* out = (float*)d_out;

    const int M     = in_sizes[0] / N_DIM;     // 16384
    const int batch = M / T_LEN;               // 8
    const int nChunks = T_LEN / CHUNK;

    float *Bu_p; cudaGetSymbolAddress((void**)&Bu_p, g_Bu);
    __half *uh, *Xh, *Bh, *Ch, *Dh;
    cudaGetSymbolAddress((void**)&uh, g_uh);
    cudaGetSymbolAddress((void**)&Xh, g_Xh);
    cudaGetSymbolAddress((void**)&Bh, g_Bh);
    cudaGetSymbolAddress((void**)&Ch, g_Ch);
    cudaGetSymbolAddress((void**)&Dh, g_Dh);

    cudaFuncSetAttribute(gemm_mma<false>, cudaFuncAttributeMaxDynamicSharedMemorySize, GEMM_SMEM);
    cudaFuncSetAttribute(gemm_mma<true>,  cudaFuncAttributeMaxDynamicSharedMemorySize, GEMM_SMEM);

    // 0) convert operands to fp16
    const int n4_u = (M * N_DIM) / 4;          // 4M
    const int n4_m = (N_DIM * N_DIM) / 4;      // 256K
    split_f32_hi<<<(n4_u + 255) / 256, 256>>>((const float4*)u,  (uint2*)uh, n4_u);
    split_f32_hi<<<(n4_m + 255) / 256, 256>>>((const float4*)B,  (uint2*)Bh, n4_m);
    split_f32_hi<<<(n4_m + 255) / 256, 256>>>((const float4*)C,  (uint2*)Ch, n4_m);
    split_f32_hi<<<(n4_m + 255) / 256, 256>>>((const float4*)Dm, (uint2*)Dh, n4_m);

    dim3 grid(N_DIM / BN, M / BM);             // (8, 128)

    // 1) Bu = u @ B^T   (f32 out)
    gemm_mma<false><<<grid, 256, GEMM_SMEM>>>(uh, Bh, nullptr, nullptr,
                                              Bu_p, M, N_DIM, N_DIM);

    // 2) scan over T; phase3 emits X directly as fp16
    int p1_threads = batch * nChunks * N_DIM;
    scan_phase1<<<(p1_threads + 255) / 256, 256>>>(A, batch);
    scan_phase2<<<(batch * N_DIM + 255) / 256, 256>>>(A, batch);
    scan_phase3<<<(p1_threads + 255) / 256, 256>>>(A, batch);

    // 3) y = X @ C^T + u @ D^T   (dual accumulate)
    gemm_mma<true><<<grid, 256, GEMM_SMEM>>>(Xh, Ch, uh, Dh,
                                             out, M, N_DIM, N_DIM);
}

// round 8
// speedup vs baseline: 6.2450x; 1.1739x over previous
#include <cuda_runtime.h>
#include <cuda_fp16.h>
#include <cstdint>

// Problem constants (fixed): u (8,2048,1024) f32, A/B/C/D (1024,1024) f32.
constexpr int N_DIM = 1024;
constexpr int T_LEN = 2048;
constexpr int CHUNK = 64;

// Scratch (__device__ globals; no allocation allowed).
__device__ float g_carry[262144];
__device__ __half g_uh[16777216];         // u  (fp16)
__device__ __half g_Xh[16777216];         // X  (fp16; local scans then fixed up)
__device__ __half g_Bh[1048576];
__device__ __half g_Ch[1048576];
__device__ __half g_Dh[1048576];

// ---------------------------------------------------------------------------
// helpers
// ---------------------------------------------------------------------------
__device__ __forceinline__ uint32_t smem_u32(const void* p) {
    uint32_t a;
    asm("{ .reg .u64 t; cvta.to.shared.u64 t, %1; cvt.u32.u64 %0, t; }" : "=r"(a) : "l"(p));
    return a;
}
__device__ __forceinline__ void cp_async16(uint32_t dst, const void* src) {
    asm volatile("cp.async.cg.shared.global [%0], [%1], 16;" :: "r"(dst), "l"(src));
}
__device__ __forceinline__ void cp_commit() {
    asm volatile("cp.async.commit_group;");
}
__device__ __forceinline__ void cp_wait1() {
    asm volatile("cp.async.wait_group 1;");
}
__device__ __forceinline__ void ldsm4(uint32_t* r, uint32_t addr) {
    asm volatile("ldmatrix.sync.aligned.m8n8.x4.shared.b16 {%0,%1,%2,%3}, [%4];"
                 : "=r"(r[0]), "=r"(r[1]), "=r"(r[2]), "=r"(r[3]) : "r"(addr));
}
__device__ __forceinline__ void mma16816(float* d, const uint32_t* a, const uint32_t* b) {
    asm volatile(
        "mma.sync.aligned.m16n8k16.row.col.f32.f16.f16.f32 "
        "{%0,%1,%2,%3}, {%4,%5,%6,%7}, {%8,%9}, {%0,%1,%2,%3};"
        : "+f"(d[0]), "+f"(d[1]), "+f"(d[2]), "+f"(d[3])
        : "r"(a[0]), "r"(a[1]), "r"(a[2]), "r"(a[3]), "r"(b[0]), "r"(b[1]));
}
__device__ __forceinline__ uint32_t pk_f16(__half a, __half b) {
    return (uint32_t)__half_as_ushort(a) | ((uint32_t)__half_as_ushort(b) << 16);
}

// ---------------------------------------------------------------------------
// converts f32 -> f16
// ---------------------------------------------------------------------------
__global__ void conv_u(const float4* __restrict__ src, uint2* __restrict__ dst, int n4)
{
    int i = blockIdx.x * blockDim.x + threadIdx.x;
    if (i >= n4) return;
    float4 v = src[i];
    dst[i] = make_uint2(pk_f16(__float2half(v.x), __float2half(v.y)),
                        pk_f16(__float2half(v.z), __float2half(v.w)));
}

// one kernel converts B, C, D (each n4m float4's)
__global__ void conv_bcd(const float4* __restrict__ B, const float4* __restrict__ C,
                         const float4* __restrict__ D,
                         uint2* __restrict__ Bh, uint2* __restrict__ Ch,
                         uint2* __restrict__ Dh, int n4m)
{
    int i = blockIdx.x * blockDim.x + threadIdx.x;
    if (i >= 3 * n4m) return;
    const float4* s = (i < n4m) ? B : (i < 2 * n4m ? C : D);
    uint2* d        = (i < n4m) ? Bh : (i < 2 * n4m ? Ch : Dh);
    int j = (i < n4m) ? i : (i < 2 * n4m ? i - n4m : i - 2 * n4m);
    float4 v = s[j];
    d[j] = make_uint2(pk_f16(__float2half(v.x), __float2half(v.y)),
                      pk_f16(__float2half(v.z), __float2half(v.w)));
}

// ---------------------------------------------------------------------------
// fp16 NT GEMM via mma.sync: out[m,n] = sum_k A[m,k]*B[n,k] (+ A2*B2 if DUAL)
// 128x128x64 iterations, 256 threads (2x4 warps, 64x32 warp tile),
// 3-stage cp.async pipeline (36KB/stage), 2 CTAs/SM, B-frag double buffer.
// SCANEPI: instead of storing f32, run the per-chunk (64-row) scan locally and
// emit fp16 X-local + chunk carries (fuses scan_phase1 into the epilogue).
// ---------------------------------------------------------------------------
constexpr int BM = 128, BN = 128, BK = 64;
constexpr int BKP = 72;                      // halves per row incl. 16B pad
constexpr int TILE_B = BM * BKP * 2;         // 18432 bytes per matrix tile
constexpr int STAGE_B = 2 * TILE_B;          // 36864 (A + B)
constexpr int STAGES = 3;
constexpr int GEMM_SMEM = STAGES * STAGE_B;  // 110592

template <bool DUAL, bool SCANEPI>
__global__ void __launch_bounds__(256, 2)
gemm_mma(const __half* __restrict__ Ah, const __half* __restrict__ Bh,
         const __half* __restrict__ A2h, const __half* __restrict__ B2h,
         float* __restrict__ Cout,                       // normal epilogue
         const float* __restrict__ Adiag,                // scan epilogue
         __half* __restrict__ Xout, float* __restrict__ carry,
         int M, int N, int K)
{
    extern __shared__ char smem[];
    const uint32_t sbase = smem_u32(smem);
    const int tid = threadIdx.x, lane = tid & 31, wid = tid >> 5;
    const int wm = wid >> 2, wn = wid & 3;
    const int m0 = blockIdx.y * BM, n0 = blockIdx.x * BN;

    const int IPER = K / BK;                  // 16
    const int KT = DUAL ? 2 * IPER : IPER;

    float acc[4][4][4] = {};

    auto issue = [&](int kt) {
        const bool p2 = DUAL && (kt >= IPER);
        const __half* ah = p2 ? A2h : Ah;
        const __half* bh = p2 ? B2h : Bh;
        const int k0 = (kt % IPER) * BK;
        const uint32_t st = sbase + (kt % STAGES) * STAGE_B;
        #pragma unroll
        for (int i = 0; i < 4; ++i) {
            const int slot = tid + i * 256;     // 0..1023
            const int r = slot >> 3, c = slot & 7;
            const uint32_t dst = st + r * (BKP * 2) + c * 16;
            cp_async16(dst,          ah + (size_t)(m0 + r) * K + k0 + c * 8);
            cp_async16(dst + TILE_B, bh + (size_t)(n0 + r) * K + k0 + c * 8);
        }
    };

    issue(0); cp_commit();
    issue(1); cp_commit();

    // per-lane ldmatrix address bases (byte offsets within a tile)
    const uint32_t a_base = (((wm * 64 + (lane & 15)) * BKP) + ((lane >> 4) << 3)) * 2;
    const uint32_t b_base = (((wn * 32 + (lane & 7) + ((lane >> 4) << 3)) * BKP) +
                             (((lane >> 3) & 1) << 3)) * 2;

    for (int kt = 0; kt < KT; ++kt) {
        cp_wait1();                 // stage kt%3 resident for this thread
        __syncthreads();            // visible to all; all warps past stage (kt-1)
        if (kt + 2 < KT) issue(kt + 2);
        cp_commit();

        const uint32_t st = sbase + (kt % STAGES) * STAGE_B;
        const uint32_t sAh = st, sBh = st + TILE_B;

        uint32_t bfr[2][2][4];
        #pragma unroll
        for (int nj = 0; nj < 2; ++nj)
            ldsm4(bfr[0][nj], sBh + b_base + nj * (16 * BKP * 2));

        #pragma unroll
        for (int k16 = 0; k16 < 4; ++k16) {
            uint32_t afr[4][4];
            #pragma unroll
            for (int mi = 0; mi < 4; ++mi)
                ldsm4(afr[mi], sAh + a_base + mi * (16 * BKP * 2) + k16 * 32);
            if (k16 < 3) {
                #pragma unroll
                for (int nj = 0; nj < 2; ++nj)
                    ldsm4(bfr[(k16 + 1) & 1][nj],
                          sBh + b_base + nj * (16 * BKP * 2) + (k16 + 1) * 32);
            }
            #pragma unroll
            for (int mi = 0; mi < 4; ++mi)
                #pragma unroll
                for (int nf = 0; nf < 4; ++nf)
                    mma16816(acc[mi][nf], afr[mi], &bfr[k16 & 1][nf >> 1][(nf & 1) * 2]);
        }
    }

    if (!SCANEPI) {
        // normal epilogue: f32 float2 stores
        #pragma unroll
        for (int mi = 0; mi < 4; ++mi) {
            const int row0 = m0 + wm * 64 + mi * 16 + (lane >> 2);
            #pragma unroll
            for (int nf = 0; nf < 4; ++nf) {
                const int col = n0 + wn * 32 + (nf >> 1) * 16 + (nf & 1) * 8 + (lane & 3) * 2;
                *(float2*)&Cout[(size_t)row0 * N + col] =
                    make_float2(acc[mi][nf][0], acc[mi][nf][1]);
                *(float2*)&Cout[(size_t)(row0 + 8) * N + col] =
                    make_float2(acc[mi][nf][2], acc[mi][nf][3]);
            }
        }
    } else {
        // scan epilogue: stage tile through smem (129-float pitch), scan 64-row
        // chunks per column, emit fp16 X-local + chunk carry.
        __syncthreads();                       // done with pipeline smem
        float* smf = (float*)smem;             // 128 x 129 floats = 66048 B
        #pragma unroll
        for (int mi = 0; mi < 4; ++mi) {
            const int row0 = wm * 64 + mi * 16 + (lane >> 2);
            #pragma unroll
            for (int nf = 0; nf < 4; ++nf) {
                const int col = wn * 32 + (nf >> 1) * 16 + (nf & 1) * 8 + (lane & 3) * 2;
                smf[row0 * 129 + col]       = acc[mi][nf][0];
                smf[row0 * 129 + col + 1]   = acc[mi][nf][1];
                smf[(row0 + 8) * 129 + col]     = acc[mi][nf][2];
                smf[(row0 + 8) * 129 + col + 1] = acc[mi][nf][3];
            }
        }
        __syncthreads();

        const int c  = tid & 127;              // column within tile
        const int ch = tid >> 7;               // chunk 0/1 (64 rows each)
        const int ng = n0 + c;
        const float a = Adiag[(size_t)ng * N_DIM + ng];

        float x = 0.0f;
        const int rbase = ch * 64;
        #pragma unroll 8
        for (int t = 0; t < CHUNK; ++t) {
            x = fmaf(x, a, smf[(rbase + t) * 129 + c]);
            Xout[(size_t)(m0 + rbase + t) * N + ng] = __float2half(x);
        }
        const int bc = (m0 + rbase) >> 6;      // global 64-row chunk index
        carry[(size_t)bc * N_DIM + ng] = x;
    }
}

// ---------------------------------------------------------------------------
// scan combine over chunk carries + fp16 fix-up of X
// ---------------------------------------------------------------------------
__global__ void scan_phase2(const float* __restrict__ Afull, int batch)
{
    const int nChunks = T_LEN / CHUNK;
    int id = blockIdx.x * blockDim.x + threadIdx.x;
    if (id >= batch * N_DIM) return;
    int n = id & (N_DIM - 1), b = id >> 10;

    float a  = Afull[(size_t)n * N_DIM + n];
    float aC = a;
    #pragma unroll
    for (int i = 0; i < 6; ++i) aC *= aC;      // a^64

    float S = 0.0f;
    for (int c = 0; c < nChunks; ++c) {
        size_t idx = (size_t)(b * nChunks + c) * N_DIM + n;
        float L = g_carry[idx];
        g_carry[idx] = S;
        S = fmaf(aC, S, L);
    }
}

// phase3: X = Xlocal + a^{t+1} * carry (fp16 read-modify-write)
__global__ void scan_phase3(const float* __restrict__ Afull, int batch)
{
    const int nChunks = T_LEN / CHUNK;
    int id = blockIdx.x * blockDim.x + threadIdx.x;
    int n  = id & (N_DIM - 1);
    int bc = id >> 10;
    if (bc >= batch * nChunks) return;

    const float S = g_carry[(size_t)bc * N_DIM + n];
    if (S == 0.0f) return;                     // chunk 0 of each batch
    const float a = Afull[(size_t)n * N_DIM + n];
    size_t base = (size_t)bc * CHUNK * N_DIM + n;

    float f = a;
    #pragma unroll 8
    for (int t = 0; t < CHUNK; ++t) {
        size_t idx = base + (size_t)t * N_DIM;
        float x = fmaf(f, S, __half2float(g_Xh[idx]));
        f *= a;
        g_Xh[idx] = __float2half(x);
    }
}

// ---------------------------------------------------------------------------
extern "C" void kernel_launch(void* const* d_in, const int* in_sizes, int n_in,
                              void* d_out, int out_size)
{
    const float* u  = (const float*)d_in[0];   // (batch, T, m)
    const float* A  = (const float*)d_in[1];   // (n, n)
    const float* B  = (const float*)d_in[2];   // (n, m)
    const float* C  = (const float*)d_in[3];   // (p, n)
    const float* Dm = (const float*)d_in[4];   // (p, m)
    float* out = (float*)d_out;

    const int M     = in_sizes[0] / N_DIM;     // 16384
    const int batch = M / T_LEN;               // 8

    __half *uh, *Xh, *Bh, *Ch, *Dh;
    float* carry_p;
    cudaGetSymbolAddress((void**)&uh, g_uh);
    cudaGetSymbolAddress((void**)&Xh, g_Xh);
    cudaGetSymbolAddress((void**)&Bh, g_Bh);
    cudaGetSymbolAddress((void**)&Ch, g_Ch);
    cudaGetSymbolAddress((void**)&Dh, g_Dh);
    cudaGetSymbolAddress((void**)&carry_p, g_carry);

    cudaFuncSetAttribute(gemm_mma<false, true>,
                         cudaFuncAttributeMaxDynamicSharedMemorySize, GEMM_SMEM);
    cudaFuncSetAttribute(gemm_mma<true, false>,
                         cudaFuncAttributeMaxDynamicSharedMemorySize, GEMM_SMEM);

    // 0) convert operands to fp16
    const int n4_u = (M * N_DIM) / 4;          // 4M
    const int n4_m = (N_DIM * N_DIM) / 4;      // 256K
    conv_u<<<(n4_u + 255) / 256, 256>>>((const float4*)u, (uint2*)uh, n4_u);
    conv_bcd<<<(3 * n4_m + 255) / 256, 256>>>((const float4*)B, (const float4*)C,
                                              (const float4*)Dm,
                                              (uint2*)Bh, (uint2*)Ch, (uint2*)Dh, n4_m);

    dim3 grid(N_DIM / BN, M / BM);             // (8, 128)

    // 1) Bu = u @ B^T, fused with per-chunk local scan -> Xh (fp16) + carries
    gemm_mma<false, true><<<grid, 256, GEMM_SMEM>>>(uh, Bh, nullptr, nullptr,
                                                    nullptr, A, Xh, carry_p,
                                                    M, N_DIM, N_DIM);

    // 2) combine carries, then fp16 fix-up of X
    scan_phase2<<<(batch * N_DIM + 255) / 256, 256>>>(A, batch);
    int p3_threads = (M / CHUNK) * N_DIM;
    scan_phase3<<<(p3_threads + 255) / 256, 256>>>(A, batch);

    // 3) y = X @ C^T + u @ D^T   (dual accumulate)
    gemm_mma<true, false><<<grid, 256, GEMM_SMEM>>>(Xh, Ch, uh, Dh,
                                                    out, nullptr, nullptr, nullptr,
                                                    M, N_DIM, N_DIM);
}